// round 3
// baseline (speedup 1.0000x reference)
#include <cuda_runtime.h>
#include <math_constants.h>

// Problem: B=128, L=4096, FILTER_SIZE=2, N_QUBITS=4, 10 classes.
// Analytic reduction: expval_k(b,ol) = K_k * g(b,ol),
//   K_k = cos(p_k1)cos(p_k2)cos(p_k3)   (CNOT ring conjugates Z0 -> Z1Z2Z3)
//   g   = cos(x[ol,1]) * cos(x[ol+1,0]) * cos(x[ol+1,1])
// logits[j] = bias[j] + sum_ol g(ol) * (K0*W[2ol,j] + K1*W[2ol+1,j]); softmax.
#define OL    4095
#define OLP   4096
#define NCLS  10
#define B_SZ  128
#define NT    1024
#define NWARP (NT / 32)

// smem pair array P[i] = (s1[i], h[i]), i in [0, 4098); stored as 16B granules
// (2 pairs per granule) with an XOR swizzle so both the stride-16B writes and
// the stride-32B reads are bank-conflict-free.
#define SCB_BYTES (16 * 2050 + 128)

__device__ __forceinline__ float4* SW(char* s, int byteoff)
{
    return (float4*)(s + (byteoff ^ (((byteoff >> 7) & 7) << 4)));
}

__global__ __launch_bounds__(NT, 1) void qcnn_fused(const float* __restrict__ x,
                                                    const float* __restrict__ params,
                                                    const float* __restrict__ W,
                                                    const float* __restrict__ bias,
                                                    float* __restrict__ out)
{
    __shared__ __align__(16) char scb[SCB_BYTES];
    __shared__ float sred[NWARP][NCLS];

    const int b   = blockIdx.x;
    const int tid = threadIdx.x;

    // per-thread fold constants (6 MUFU, params broadcast via L1)
    const float K0 = __cosf(__ldg(&params[1])) * __cosf(__ldg(&params[2])) * __cosf(__ldg(&params[3]));
    const float K1 = __cosf(__ldg(&params[5])) * __cosf(__ldg(&params[6])) * __cosf(__ldg(&params[7]));

    // ---- phase 1: cos pass. one float4 = 2 (x0,x1) pairs -> 1 swizzled STS.128
    const float4* row4 = (const float4*)(x + (size_t)b * OLP * 2);
#pragma unroll
    for (int k = 0; k < 2; ++k) {
        int i = tid + k * NT;                 // granule index 0..2047
        float4 v = row4[i];
        float c1a = __cosf(v.y), ha = __cosf(v.x) * c1a;
        float c1b = __cosf(v.w), hb = __cosf(v.z) * c1b;
        *SW(scb, 16 * i) = make_float4(c1a, ha, c1b, hb);
    }
    if (tid < 2)                              // zero pad granules 2048,2049
        *SW(scb, 16 * (2048 + tid)) = make_float4(0.f, 0.f, 0.f, 0.f);
    __syncthreads();

    // ---- phase 2: 4 consecutive windows per thread
    float4 A  = *SW(scb, 32 * tid);           // P[4t],P[4t+1]
    float4 Bv = *SW(scb, 32 * tid + 16);      // P[4t+2],P[4t+3]
    float4 C  = *SW(scb, 32 * tid + 32);      // P[4t+4],P[4t+5]
    float g[4];
    g[0] = A.x  * A.w;                        // s1[4t]  * h[4t+1]
    g[1] = A.z  * Bv.y;
    g[2] = Bv.x * Bv.w;
    g[3] = Bv.z * C.y;                        // =0 for the padded window 4095

    float acc[NCLS];
#pragma unroll
    for (int j = 0; j < NCLS; ++j) acc[j] = 0.0f;

    // W is [8190][10] row-major = 20475 float4. Thread t's 4 windows use
    // W rows 8t..8t+7 = float4 indices [20t, 20t+20): contiguous & coalesced.
    const float4* W4 = (const float4*)W;
    const int wbase = tid * 20;
#pragma unroll
    for (int w = 0; w < 4; ++w) {
        int wb = wbase + 5 * w;
        if (wb > 20470) wb = 20470;           // clamp OOB rows of padded window (g=0)
        float4 r0 = W4[wb    ];               // even row floats 0-3
        float4 r1 = W4[wb + 1];               // even row floats 4-7
        float4 r2 = W4[wb + 2];               // even 8-9 | odd 0-1
        float4 r3 = W4[wb + 3];               // odd 2-5
        float4 r4 = W4[wb + 4];               // odd 6-9
        float gw = g[w];
        float f;
        f = fmaf(K1, r2.z, K0 * r0.x); acc[0] = fmaf(gw, f, acc[0]);
        f = fmaf(K1, r2.w, K0 * r0.y); acc[1] = fmaf(gw, f, acc[1]);
        f = fmaf(K1, r3.x, K0 * r0.z); acc[2] = fmaf(gw, f, acc[2]);
        f = fmaf(K1, r3.y, K0 * r0.w); acc[3] = fmaf(gw, f, acc[3]);
        f = fmaf(K1, r3.z, K0 * r1.x); acc[4] = fmaf(gw, f, acc[4]);
        f = fmaf(K1, r3.w, K0 * r1.y); acc[5] = fmaf(gw, f, acc[5]);
        f = fmaf(K1, r4.x, K0 * r1.z); acc[6] = fmaf(gw, f, acc[6]);
        f = fmaf(K1, r4.y, K0 * r1.w); acc[7] = fmaf(gw, f, acc[7]);
        f = fmaf(K1, r4.z, K0 * r2.x); acc[8] = fmaf(gw, f, acc[8]);
        f = fmaf(K1, r4.w, K0 * r2.y); acc[9] = fmaf(gw, f, acc[9]);
    }

    // ---- reduce 1024 threads -> 10 logits
#pragma unroll
    for (int j = 0; j < NCLS; ++j) {
#pragma unroll
        for (int off = 16; off; off >>= 1)
            acc[j] += __shfl_xor_sync(0xFFFFFFFFu, acc[j], off);
    }
    const int warp = tid >> 5, lane = tid & 31;
    if (lane == 0) {
#pragma unroll
        for (int j = 0; j < NCLS; ++j) sred[warp][j] = acc[j];
    }
    __syncthreads();

    // ---- final reduce + softmax in warp 0 (lanes 0..9 own one class)
    if (tid < 32) {
        float logit = -CUDART_INF_F;
        if (tid < NCLS) {
            logit = bias[tid];
#pragma unroll
            for (int w = 0; w < NWARP; ++w) logit += sred[w][tid];
        }
        float mx = logit;
#pragma unroll
        for (int off = 16; off; off >>= 1)
            mx = fmaxf(mx, __shfl_xor_sync(0xFFFFFFFFu, mx, off));
        float e = (tid < NCLS) ? __expf(logit - mx) : 0.0f;
        float s = e;
#pragma unroll
        for (int off = 16; off; off >>= 1)
            s += __shfl_xor_sync(0xFFFFFFFFu, s, off);
        if (tid < NCLS) out[b * NCLS + tid] = e / s;
    }
}

// Inputs (metadata order): inputs(128*4096*2 f32), params(8 f32),
//                          W(8190*10 f32), b(10 f32). Output: (128*10) f32.
extern "C" void kernel_launch(void* const* d_in, const int* in_sizes, int n_in,
                              void* d_out, int out_size)
{
    const float* inputs = (const float*)d_in[0];
    const float* params = (const float*)d_in[1];
    const float* W      = (const float*)d_in[2];
    const float* bias   = (const float*)d_in[3];
    float* out          = (float*)d_out;

    qcnn_fused<<<B_SZ, NT>>>(inputs, params, W, bias, out);
}

// round 4
// speedup vs baseline: 1.7509x; 1.7509x over previous
#include <cuda_runtime.h>
#include <math_constants.h>

// Problem: B=128, L=4096, FILTER_SIZE=2, N_QUBITS=4, 10 classes.
// Analytic reduction: expval_k(b,ol) = K_k * g(b,ol),
//   K_k = cos(p_k1)cos(p_k2)cos(p_k3)   (CNOT ring conjugates Z0 -> Z1Z2Z3)
//   g   = cos(x[ol,1]) * cos(x[ol+1,0]) * cos(x[ol+1,1])
// logits[j] = bias[j] + sum_ol g(ol)*(K0*W[2ol,j]+K1*W[2ol+1,j]); softmax.
#define OL    4095
#define OLP   4096
#define NCLS  10
#define B_SZ  128
#define NT    1024
#define NWARP (NT / 32)

// Folded, TRANSPOSED weights: d_Wp[j*OLP + ol] (transpose => main's loads are
// lane-stride-16B coalesced; round-3 showed direct W reads are 8x wavefronts).
__device__ __align__(16) float d_Wp[NCLS * OLP];

// ---------------------------------------------------------------------------
// Prep: 32 blocks x 256 threads, 128 ol per block.
// Stage the W slice (2560 floats) in smem via coalesced float4 loads, then
// write d_Wp coalesced. OOB tail (rows 8190/8191 of padded ol=4095) -> 0.
// ---------------------------------------------------------------------------
__global__ __launch_bounds__(256) void qcnn_prep(const float* __restrict__ params,
                                                 const float* __restrict__ W)
{
    __shared__ float sw[2560];
    const int bid = blockIdx.x, tid = threadIdx.x;
    const int W_F4 = 20475;                       // total float4 in W (81900 floats)

    const float4* w4 = (const float4*)W;
    const int f4base = bid * 640;
#pragma unroll
    for (int k = 0; k < 3; ++k) {                 // 640 float4 per block, 256 thr
        int li = tid + k * 256;
        if (li < 640) {
            int gi = f4base + li;
            float4 v = (gi < W_F4) ? w4[gi] : make_float4(0.f, 0.f, 0.f, 0.f);
            *(float4*)&sw[4 * li] = v;
        }
    }
    __syncthreads();

    if (tid < 128) {
        float K0 = __cosf(params[1]) * __cosf(params[2]) * __cosf(params[3]);
        float K1 = __cosf(params[5]) * __cosf(params[6]) * __cosf(params[7]);
        int ol = bid * 128 + tid;
        const float* r = &sw[20 * tid];           // rows 2ol (10 floats), 2ol+1
#pragma unroll
        for (int j = 0; j < NCLS; ++j)
            d_Wp[j * OLP + ol] = fmaf(K1, r[10 + j], K0 * r[j]);
    }
}

// ---------------------------------------------------------------------------
// Main: one block (1024 threads) per batch row, 4 windows per thread.
// No smem staging: pair 4t+4 comes from shfl.down of the neighbor's raw x
// (lane 31 loads one float2 from gmem). Then 10 coalesced LDG.128 of d_Wp.
// ---------------------------------------------------------------------------
__global__ __launch_bounds__(NT, 1) void qcnn_main(const float* __restrict__ x,
                                                   const float* __restrict__ bias,
                                                   float* __restrict__ out)
{
    __shared__ float sred[NWARP][NCLS];

    const int b   = blockIdx.x;
    const int tid = threadIdx.x;

    // x pairs 4t..4t+3 (two float4 = 32B per thread)
    const float4* row4 = (const float4*)(x + (size_t)b * OLP * 2);
    float4 v0 = row4[2 * tid];
    float4 v1 = row4[2 * tid + 1];

    // neighbor pair 4t+4 = (x[8t+8], x[8t+9]) via shuffle; lane 31 from gmem
    float nx = __shfl_down_sync(0xFFFFFFFFu, v0.x, 1);
    float ny = __shfl_down_sync(0xFFFFFFFFu, v0.y, 1);
    if ((tid & 31) == 31) {
        int off = (tid == 1023) ? 0 : 8 * tid + 8;   // tid=1023: value unused (g3=0)
        float2 nb = *(const float2*)(x + (size_t)b * OLP * 2 + off);
        nx = nb.x; ny = nb.y;
    }

    // s1[i]=cos(x1), h[i]=cos(x0)*s1[i];  g_k = s1[k]*h[k+1]
    float s1_0 = __cosf(v0.y);
    float s1_1 = __cosf(v0.w), h1 = __cosf(v0.z) * s1_1;
    float s1_2 = __cosf(v1.y), h2 = __cosf(v1.x) * s1_2;
    float s1_3 = __cosf(v1.w), h3 = __cosf(v1.z) * s1_3;
    float h4 = __cosf(nx) * __cosf(ny);
    float g0 = s1_0 * h1;
    float g1 = s1_1 * h2;
    float g2 = s1_2 * h3;
    float g3 = (tid == 1023) ? 0.0f : s1_3 * h4;     // window 4095 is padding

    // dot with folded weights: 10 coalesced, L2-hot LDG.128
    const float4* Wp4 = (const float4*)d_Wp;
    float acc[NCLS];
#pragma unroll
    for (int j = 0; j < NCLS; ++j) {
        float4 w = Wp4[j * (OLP / 4) + tid];
        float a;
        a = g0 * w.x;
        a = fmaf(g1, w.y, a);
        a = fmaf(g2, w.z, a);
        a = fmaf(g3, w.w, a);
        acc[j] = a;
    }

    // reduce 1024 threads -> 10 logits
#pragma unroll
    for (int j = 0; j < NCLS; ++j) {
#pragma unroll
        for (int off = 16; off; off >>= 1)
            acc[j] += __shfl_xor_sync(0xFFFFFFFFu, acc[j], off);
    }
    const int warp = tid >> 5, lane = tid & 31;
    if (lane == 0) {
#pragma unroll
        for (int j = 0; j < NCLS; ++j) sred[warp][j] = acc[j];
    }
    __syncthreads();

    // final reduce + softmax in warp 0 (lanes 0..9 own one class)
    if (tid < 32) {
        float logit = -CUDART_INF_F;
        if (tid < NCLS) {
            logit = bias[tid];
#pragma unroll
            for (int w = 0; w < NWARP; ++w) logit += sred[w][tid];
        }
        float mx = logit;
#pragma unroll
        for (int off = 16; off; off >>= 1)
            mx = fmaxf(mx, __shfl_xor_sync(0xFFFFFFFFu, mx, off));
        float e = (tid < NCLS) ? __expf(logit - mx) : 0.0f;
        float s = e;
#pragma unroll
        for (int off = 16; off; off >>= 1)
            s += __shfl_xor_sync(0xFFFFFFFFu, s, off);
        if (tid < NCLS) out[b * NCLS + tid] = e / s;
    }
}

// Inputs (metadata order): inputs(128*4096*2 f32), params(8 f32),
//                          W(8190*10 f32), b(10 f32). Output: (128*10) f32.
extern "C" void kernel_launch(void* const* d_in, const int* in_sizes, int n_in,
                              void* d_out, int out_size)
{
    const float* inputs = (const float*)d_in[0];
    const float* params = (const float*)d_in[1];
    const float* W      = (const float*)d_in[2];
    const float* bias   = (const float*)d_in[3];
    float* out          = (float*)d_out;

    qcnn_prep<<<32, 256>>>(params, W);
    qcnn_main<<<B_SZ, NT>>>(inputs, bias, out);
}